// round 15
// baseline (speedup 1.0000x reference)
#include <cuda_runtime.h>
#include <cuda_bf16.h>
#include <cuda_fp16.h>
#include <cuda_fp8.h>
#include <cstdint>

#define NB 8
#define NC 512
#define NM 64
#define NN 4096
#define NI 640
#define EPSF 1e-6f
#define NSPLIT 16

// ---------------------------------------------------------------- scratch
__device__ __align__(16) unsigned char gW8[NI * NC];
__device__ float gBiasF[NI];
__device__ __align__(16) unsigned char gX8[(size_t)NB * NN * NC];    // fp8 x, [b,n,c]
__device__ __align__(16) unsigned char gV8[(size_t)NB * NC * NN];    // fp8 V, [b,c,n]
__device__ __align__(16) unsigned char gKn8[(size_t)NB * NM * NN];   // fp8 Kn*16, [b,m,n]
__device__ __align__(16) __nv_bfloat16 gQnTh[(size_t)NB * NN * NM];  // [b,n,m]
__device__ __align__(16) __nv_bfloat16 gMatP[(size_t)NSPLIT * NB * NC * NM]; // bf16 partials
__device__ __align__(16) __nv_bfloat16 gMatTh[(size_t)NB * NC * NM]; // [b,c,m]
__device__ float gVsumP[(size_t)32 * NB * NC];   // [nblk,b,c]
__device__ float gKsumP[(size_t)32 * NB * NM];   // [nblk,b,m]
__device__ float gKsum[NB * NM];
__device__ float gVsum[NB * NC];

// ---------------------------------------------------------------- helpers
__device__ __forceinline__ uint32_t smem_to_u32(const void* p) {
    uint32_t a;
    asm("{ .reg .u64 t; cvta.to.shared.u64 t, %1; cvt.u32.u64 %0, t; }" : "=r"(a) : "l"(p));
    return a;
}
__device__ __forceinline__ void ldsm4(uint32_t& r0, uint32_t& r1, uint32_t& r2,
                                      uint32_t& r3, uint32_t addr) {
    asm volatile("ldmatrix.sync.aligned.m8n8.x4.shared.b16 {%0,%1,%2,%3}, [%4];"
                 : "=r"(r0), "=r"(r1), "=r"(r2), "=r"(r3) : "r"(addr));
}
__device__ __forceinline__ void mma_bf16(float* d, const uint32_t* a, const uint32_t* b) {
    asm volatile(
        "mma.sync.aligned.m16n8k16.row.col.f32.bf16.bf16.f32 "
        "{%0,%1,%2,%3}, {%4,%5,%6,%7}, {%8,%9}, {%0,%1,%2,%3};"
        : "+f"(d[0]), "+f"(d[1]), "+f"(d[2]), "+f"(d[3])
        : "r"(a[0]), "r"(a[1]), "r"(a[2]), "r"(a[3]), "r"(b[0]), "r"(b[1]));
}
// fp8 mma with f16 accumulators (2 regs = 4 halves) — halves register pressure
__device__ __forceinline__ void mma_fp8_h(uint32_t* d, const uint32_t* a, const uint32_t* b) {
    asm volatile(
        "mma.sync.aligned.m16n8k32.row.col.f16.e4m3.e4m3.f16 "
        "{%0,%1}, {%2,%3,%4,%5}, {%6,%7}, {%0,%1};"
        : "+r"(d[0]), "+r"(d[1])
        : "r"(a[0]), "r"(a[1]), "r"(a[2]), "r"(a[3]), "r"(b[0]), "r"(b[1]));
}
__device__ __forceinline__ void cp_async16(uint32_t dst, const void* src) {
    asm volatile("cp.async.cg.shared.global [%0], [%1], 16;" :: "r"(dst), "l"(src));
}
#define CP_COMMIT() asm volatile("cp.async.commit_group;" ::: "memory")
#define CP_WAIT1() asm volatile("cp.async.wait_group 1;" ::: "memory")
#define CP_WAIT0() asm volatile("cp.async.wait_group 0;" ::: "memory")

#define PITCH 72     // bf16 elems per smem row (144 B)
#define PITCHB 144   // bytes per fp8 smem row
#define QKPITCH 130  // bf16 pitch for epilogue QK tile

// ---------------------------------------------------------------- weights -> fp8 (x64)
__global__ void pack_weights(const float* __restrict__ Wq, const float* __restrict__ bq,
                             const float* __restrict__ Wk, const float* __restrict__ bk,
                             const float* __restrict__ Wv, const float* __restrict__ bv) {
    int i = blockIdx.x, t = threadIdx.x;
    const float* src; float bs;
    if (i < 64) { src = Wq + (size_t)i * NC; bs = bq[i]; }
    else if (i < 128) { src = Wk + (size_t)(i - 64) * NC; bs = bk[i - 64]; }
    else { src = Wv + (size_t)(i - 128) * NC; bs = bv[i - 128]; }
    unsigned char* dst = gW8 + (size_t)i * NC;
    for (int c = t; c < NC; c += 256)
        dst[c] = __nv_cvt_float_to_fp8(src[c] * 64.0f, __NV_SATFINITE, __NV_E4M3);
    if (t == 0) gBiasF[i] = bs;
}

// ---------------------------------------------------------------- x fp32[c,n] -> fp8[n,c]
// Block: 32-n x 512-c slab. Coalesced 128B fp32 row reads; full 512B fp8 row writes.
__global__ void convert_x(const float* __restrict__ x) {
    __shared__ __align__(16) unsigned char s8[32 * 528];  // [n][c], pitch 528 (16-aligned)
    int t = threadIdx.x;
    int n0 = blockIdx.x << 5, b = blockIdx.y;
#pragma unroll
    for (int p = 0; p < 2; p++) {
        int c = (p << 8) + t;
        const float4* src = (const float4*)(x + ((size_t)b * NC + c) * NN + n0);
#pragma unroll
        for (int q = 0; q < 8; q++) {
            float4 v = src[q];
            s8[(q * 4 + 0) * 528 + c] = __nv_cvt_float_to_fp8(v.x, __NV_SATFINITE, __NV_E4M3);
            s8[(q * 4 + 1) * 528 + c] = __nv_cvt_float_to_fp8(v.y, __NV_SATFINITE, __NV_E4M3);
            s8[(q * 4 + 2) * 528 + c] = __nv_cvt_float_to_fp8(v.z, __NV_SATFINITE, __NV_E4M3);
            s8[(q * 4 + 3) * 528 + c] = __nv_cvt_float_to_fp8(v.w, __NV_SATFINITE, __NV_E4M3);
        }
    }
    __syncthreads();
    int row = t >> 3, col0 = (t & 7) << 6;  // 8 threads per 512B row, 64B each
    uint4* dst = (uint4*)(gX8 + ((size_t)b * NN + n0 + row) * NC + col0);
    const uint4* srcs = (const uint4*)(s8 + row * 528 + col0);
    dst[0] = srcs[0]; dst[1] = srcs[1]; dst[2] = srcs[2]; dst[3] = srcs[3];
}

// ---------------------------------------------------------------- profiling-slot dummy
__global__ void dummy_k() {}

// ---------------------------------------------------------------- fused QKV conv (fp8, f16 acc, 2-stage, 3 CTAs/SM)
#define STAGEB 36864
__global__ void __launch_bounds__(256, 3) conv_mma() {
    extern __shared__ __align__(16) unsigned char dsm[];
    uint32_t base = smem_to_u32(dsm);
    int t = threadIdx.x, wid = t >> 5, lane = t & 31;
    int bi = blockIdx.x << 7, bn = blockIdx.y << 7, b = blockIdx.z;
    int wm = wid & 1, wn = wid >> 1;
    const unsigned char* Ag = gW8 + (size_t)bi * NC;
    const unsigned char* Bg = gX8 + ((size_t)b * NN + bn) * NC;
    uint32_t acc[4][4][2] = {};   // f16x2 accumulators: 32 regs
    int g = lane >> 3, lr = lane & 7;
    uint32_t aOff = (uint32_t)((wm * 64 + (g & 1) * 8 + lr) * PITCHB + (g >> 1) * 16);
    uint32_t bOff = 18432u + (uint32_t)((wn * 32 + (g >> 1) * 8 + lr) * PITCHB + (g & 1) * 16);
    int lrow = t >> 1, lcol = (t & 1) * 64;

#define CONV_PREFETCH(CH, ST) do { \
        int kb_ = (CH) * 128; \
        uint32_t s_ = (uint32_t)((ST) * STAGEB); \
        const unsigned char* a_ = Ag + (size_t)lrow * NC + kb_ + lcol; \
        uint32_t da_ = base + s_ + (uint32_t)(lrow * PITCHB + lcol); \
        cp_async16(da_, a_); cp_async16(da_ + 16, a_ + 16); \
        cp_async16(da_ + 32, a_ + 32); cp_async16(da_ + 48, a_ + 48); \
        const unsigned char* b_ = Bg + (size_t)lrow * NC + kb_ + lcol; \
        uint32_t db_ = base + s_ + 18432u + (uint32_t)(lrow * PITCHB + lcol); \
        cp_async16(db_, b_); cp_async16(db_ + 16, b_ + 16); \
        cp_async16(db_ + 32, b_ + 32); cp_async16(db_ + 48, b_ + 48); \
        CP_COMMIT(); \
    } while (0)

    CONV_PREFETCH(0, 0);

    for (int ch = 0; ch < 4; ch++) {
        CP_WAIT0();
        __syncthreads();
        if (ch < 3) CONV_PREFETCH(ch + 1, (ch + 1) & 1);
        uint32_t stg = base + (uint32_t)((ch & 1) * STAGEB);
#pragma unroll
        for (int ks = 0; ks < 4; ks++) {
            int kkb = ks * 32;
            uint32_t a[4][4], bf[4][2];
#pragma unroll
            for (int mi = 0; mi < 4; mi++)
                ldsm4(a[mi][0], a[mi][1], a[mi][2], a[mi][3],
                      stg + aOff + mi * (16 * PITCHB) + kkb);
#pragma unroll
            for (int p = 0; p < 2; p++) {
                uint32_t r0, r1, r2, r3;
                ldsm4(r0, r1, r2, r3, stg + bOff + p * (16 * PITCHB) + kkb);
                bf[2 * p][0] = r0; bf[2 * p][1] = r1;
                bf[2 * p + 1][0] = r2; bf[2 * p + 1][1] = r3;
            }
#pragma unroll
            for (int mi = 0; mi < 4; mi++)
#pragma unroll
                for (int ni = 0; ni < 4; ni++)
                    mma_fp8_h(acc[mi][ni], a[mi], bf[ni]);
        }
    }
    __syncthreads();  // guard: epilogue aliases stage smem

    const float INV64 = 0.015625f;
    int r = lane >> 2, cp = (lane & 3) << 1;

    if (bi == 0) {
        // -------- fused Q/K normalize epilogue --------
        __nv_bfloat16* sQK = (__nv_bfloat16*)dsm;  // [128][QKPITCH], aliases stage0
#pragma unroll
        for (int mi = 0; mi < 4; mi++) {
#pragma unroll
            for (int half = 0; half < 2; half++) {
                int localrow = wm * 64 + mi * 16 + half * 8 + r;
                float bias = gBiasF[localrow];
#pragma unroll
                for (int ni = 0; ni < 4; ni++) {
                    __half2 hv = *(__half2*)&acc[mi][ni][half];
                    float vx = __half2float(__low2half(hv)) * INV64 + bias;
                    float vy = __half2float(__high2half(hv)) * INV64 + bias;
                    __nv_bfloat162 v = __floats2bfloat162_rn(vx, vy);
                    *(uint32_t*)&sQK[localrow * QKPITCH + wn * 32 + ni * 8 + cp] =
                        *(uint32_t*)&v;
                }
            }
        }
        __syncthreads();
        int c = t & 127, part = t >> 7;
        if (part == 0) {
            float sq = 0.f;
#pragma unroll
            for (int m = 0; m < 64; m++) {
                float v = __bfloat162float(sQK[m * QKPITCH + c]);
                sq += v * v;
            }
            float rq = rsqrtf(sq + 1e-30f);
            __nv_bfloat16 tmp[64];
#pragma unroll
            for (int m = 0; m < 64; m++)
                tmp[m] = __float2bfloat16(__bfloat162float(sQK[m * QKPITCH + c]) * rq);
            uint4* dst = (uint4*)(gQnTh + ((size_t)b * NN + bn + c) * NM);
            const uint4* srcv = (const uint4*)tmp;
#pragma unroll
            for (int q8 = 0; q8 < 8; q8++) dst[q8] = srcv[q8];
        } else {
            float sk = 0.f;
#pragma unroll
            for (int m = 0; m < 64; m++) {
                float v = __bfloat162float(sQK[(64 + m) * QKPITCH + c]);
                sk += v * v;
            }
            float rk = rsqrtf(sk + 1e-30f);
#pragma unroll
            for (int m = 0; m < 64; m++) {
                float v = __bfloat162float(sQK[(64 + m) * QKPITCH + c]);
                float kn = v * rk;
                sQK[(64 + m) * QKPITCH + c] = __float2bfloat16(kn);
                gKn8[((size_t)b * NM + m) * NN + bn + c] =
                    __nv_cvt_float_to_fp8(kn * 16.0f, __NV_SATFINITE, __NV_E4M3);
            }
        }
        __syncthreads();
        int m = t >> 2, q = t & 3;
        float s = 0.f;
#pragma unroll
        for (int cc = 0; cc < 32; cc++)
            s += __bfloat162float(sQK[(64 + m) * QKPITCH + q * 32 + cc]);
        s += __shfl_xor_sync(0xFFFFFFFFu, s, 1);
        s += __shfl_xor_sync(0xFFFFFFFFu, s, 2);
        if (q == 0) gKsumP[((size_t)blockIdx.y * NB + b) * NM + m] = s;
    } else {
        // -------- V epilogue (fp8 out); sVs aliases stage smem --------
        float* sVs = (float*)dsm;  // [4][128]
#pragma unroll
        for (int mi = 0; mi < 4; mi++) {
#pragma unroll
            for (int half = 0; half < 2; half++) {
                int localrow = wm * 64 + mi * 16 + half * 8 + r;
                int ig = bi + localrow;
                float bias = gBiasF[ig];
                unsigned char* dst = gV8 + ((size_t)b * NC + ig - 128) * NN + bn + wn * 32;
                float rowsum = 0.f;
#pragma unroll
                for (int ni = 0; ni < 4; ni++) {
                    __half2 hv = *(__half2*)&acc[mi][ni][half];
                    float vx = __half2float(__low2half(hv)) * INV64 + bias;
                    float vy = __half2float(__high2half(hv)) * INV64 + bias;
                    rowsum += vx + vy;
                    uint16_t pk =
                        (uint16_t)__nv_cvt_float_to_fp8(vx, __NV_SATFINITE, __NV_E4M3) |
                        ((uint16_t)__nv_cvt_float_to_fp8(vy, __NV_SATFINITE, __NV_E4M3) << 8);
                    *(uint16_t*)&dst[ni * 8 + cp] = pk;
                }
                rowsum += __shfl_xor_sync(0xFFFFFFFFu, rowsum, 1);
                rowsum += __shfl_xor_sync(0xFFFFFFFFu, rowsum, 2);
                if ((lane & 3) == 0) sVs[wn * 128 + localrow] = rowsum;
            }
        }
        __syncthreads();
        if (t < 128) {
            float vp = sVs[0 * 128 + t] + sVs[1 * 128 + t] + sVs[2 * 128 + t] + sVs[3 * 128 + t];
            int c = bi - 128 + t;
            gVsumP[((size_t)blockIdx.y * NB + b) * NC + c] = vp;
        }
    }
}

// ---------------------------------------------------------------- KV contraction (fp8, f16 acc, 4 CTAs/SM)
#define KVSTAGE 27648  // A 128*144 + B 64*144
__global__ void __launch_bounds__(256, 4) kv_mma() {
    extern __shared__ __align__(16) unsigned char dsm[];
    uint32_t base = smem_to_u32(dsm);
    int t = threadIdx.x, wid = t >> 5, lane = t & 31;
    int bc = blockIdx.x << 7, split = blockIdx.y, b = blockIdx.z;
    int wm = wid & 3, wn = wid >> 2;
    const unsigned char* Ag = gV8 + ((size_t)b * NC + bc) * NN + split * 256;
    const unsigned char* Bg = gKn8 + (size_t)b * NM * NN + split * 256;
    uint32_t acc[2][4][2] = {};   // f16x2 accumulators: 16 regs
    int g = lane >> 3, lr = lane & 7;
    uint32_t aOff = (uint32_t)((wm * 32 + (g & 1) * 8 + lr) * PITCHB + (g >> 1) * 16);
    uint32_t bOff = 18432u + (uint32_t)((wn * 32 + (g >> 1) * 8 + lr) * PITCHB + (g & 1) * 16);
    int ar = t >> 1, acB = (t & 1) * 64;
    int br = t >> 2, bcB = (t & 3) * 32;

#define KV_PREFETCH(CH, ST) do { \
        int kb_ = (CH) * 128; \
        uint32_t s_ = (uint32_t)((ST) * KVSTAGE); \
        const unsigned char* a_ = Ag + (size_t)ar * NN + kb_ + acB; \
        uint32_t da_ = base + s_ + (uint32_t)(ar * PITCHB + acB); \
        cp_async16(da_, a_); cp_async16(da_ + 16, a_ + 16); \
        cp_async16(da_ + 32, a_ + 32); cp_async16(da_ + 48, a_ + 48); \
        const unsigned char* b_ = Bg + (size_t)br * NN + kb_ + bcB; \
        uint32_t db_ = base + s_ + 18432u + (uint32_t)(br * PITCHB + bcB); \
        cp_async16(db_, b_); cp_async16(db_ + 16, b_ + 16); \
        CP_COMMIT(); \
    } while (0)

    KV_PREFETCH(0, 0);

    for (int ch = 0; ch < 2; ch++) {
        if (ch < 1) { KV_PREFETCH(1, 1); CP_WAIT1(); }
        else CP_WAIT0();
        __syncthreads();
        uint32_t stg = base + (uint32_t)((ch & 1) * KVSTAGE);
#pragma unroll
        for (int ks = 0; ks < 4; ks++) {
            int kkb = ks * 32;
            uint32_t a[2][4], bf[4][2];
#pragma unroll
            for (int mi = 0; mi < 2; mi++)
                ldsm4(a[mi][0], a[mi][1], a[mi][2], a[mi][3],
                      stg + aOff + mi * (16 * PITCHB) + kkb);
#pragma unroll
            for (int p = 0; p < 2; p++) {
                uint32_t r0, r1, r2, r3;
                ldsm4(r0, r1, r2, r3, stg + bOff + p * (16 * PITCHB) + kkb);
                bf[2 * p][0] = r0; bf[2 * p][1] = r1;
                bf[2 * p + 1][0] = r2; bf[2 * p + 1][1] = r3;
            }
#pragma unroll
            for (int mi = 0; mi < 2; mi++)
#pragma unroll
                for (int ni = 0; ni < 4; ni++)
                    mma_fp8_h(acc[mi][ni], a[mi], bf[ni]);
        }
        __syncthreads();
    }

    const float INV16 = 0.0625f;
    int r = lane >> 2, cp = (lane & 3) << 1;
#pragma unroll
    for (int mi = 0; mi < 2; mi++) {
#pragma unroll
        for (int half = 0; half < 2; half++) {
            int c = bc + wm * 32 + mi * 16 + half * 8 + r;
            __nv_bfloat16* dst = gMatP + (((size_t)split * NB + b) * NC + c) * NM + wn * 32;
#pragma unroll
            for (int ni = 0; ni < 4; ni++) {
                __half2 hv = *(__half2*)&acc[mi][ni][half];
                __nv_bfloat162 v = __floats2bfloat162_rn(
                    __half2float(__low2half(hv)) * INV16,
                    __half2float(__high2half(hv)) * INV16);
                *(uint32_t*)&dst[ni * 8 + cp] = *(uint32_t*)&v;
            }
        }
    }
}

// ---------------------------------------------------------------- combined reductions
__global__ void reduce_all() {
    int idx = blockIdx.x * 256 + threadIdx.x;
    const int NMAT = NB * NC * NM;
    const int NVS = NB * NC;
    if (idx < NMAT) {
        float s = 0.f;
#pragma unroll
        for (int sp = 0; sp < NSPLIT; sp++)
            s += __bfloat162float(gMatP[(size_t)sp * NMAT + idx]);
        gMatTh[idx] = __float2bfloat16(s);
    } else if (idx < NMAT + NVS) {
        int i = idx - NMAT;
        int b = i >> 9, c = i & 511;
        float s = 0.f;
#pragma unroll
        for (int blk = 0; blk < 32; blk++)
            s += gVsumP[((size_t)blk * NB + b) * NC + c];
        gVsum[b * NC + c] = s;
    } else if (idx < NMAT + NVS + NB * NM) {
        int i = idx - NMAT - NVS;
        int b = i >> 6, m = i & 63;
        float s = 0.f;
#pragma unroll
        for (int blk = 0; blk < 32; blk++)
            s += gKsumP[((size_t)blk * NB + b) * NM + m];
        gKsum[b * NM + m] = s;
    }
}

// ---------------------------------------------------------------- final GEMM + tailor + epilogue
__global__ void final_mma(const float* __restrict__ x, const float* __restrict__ gamma,
                          float* __restrict__ out) {
    __shared__ __align__(16) __nv_bfloat16 As[128][PITCH];
    __shared__ __align__(16) __nv_bfloat16 Bs[128][PITCH];
    __shared__ float ksS[64];
    __shared__ float tailorS[128];
    int t = threadIdx.x, wid = t >> 5, lane = t & 31;
    int bc = blockIdx.x << 7, bn = blockIdx.y << 7, b = blockIdx.z;
    int wm = wid & 1, wn = wid >> 1;
    const __nv_bfloat16* Ag = gMatTh + ((size_t)b * NC + bc) * NM;
    const __nv_bfloat16* Bg = gQnTh + ((size_t)b * NN + bn) * NM;
    float acc[4][4][4] = {};
    uint32_t aBase = smem_to_u32(As), bBase = smem_to_u32(Bs);
    int g = lane >> 3, lr = lane & 7;
    uint32_t aAddr = aBase + (uint32_t)(((wm * 64 + (g & 1) * 8 + lr) * PITCH + (g >> 1) * 8) * 2);
    uint32_t bAddr = bBase + (uint32_t)(((wn * 32 + (g >> 1) * 8 + lr) * PITCH + (g & 1) * 8) * 2);
    {
        int row = t >> 1, col = (t & 1) * 32;
        const uint4* sa = (const uint4*)(Ag + (size_t)row * NM + col);
        uint4* da = (uint4*)(&As[row][col]);
        da[0] = sa[0]; da[1] = sa[1]; da[2] = sa[2]; da[3] = sa[3];
        const uint4* sb = (const uint4*)(Bg + (size_t)row * NM + col);
        uint4* db = (uint4*)(&Bs[row][col]);
        db[0] = sb[0]; db[1] = sb[1]; db[2] = sb[2]; db[3] = sb[3];
    }
    if (t < 64) ksS[t] = gKsum[b * NM + t] + EPSF;
    __syncthreads();
    if (t < 128) {
        const __nv_bfloat162* qr = (const __nv_bfloat162*)&Bs[t][0];
        float s = 0.f;
#pragma unroll
        for (int mm = 0; mm < 32; mm++) {
            float2 f = __bfloat1622float2(qr[mm]);
            s += f.x * ksS[2 * mm] + f.y * ksS[2 * mm + 1];
        }
        tailorS[t] = 1.0f / ((float)NN + s);
    }
    __syncthreads();
#pragma unroll
    for (int ks = 0; ks < 4; ks++) {
        int kk = ks * 32;
        uint32_t a[4][4], bf[4][2];
#pragma unroll
        for (int mi = 0; mi < 4; mi++)
            ldsm4(a[mi][0], a[mi][1], a[mi][2], a[mi][3],
                  aAddr + mi * (16 * PITCH * 2) + kk);
#pragma unroll
        for (int p = 0; p < 2; p++) {
            uint32_t r0, r1, r2, r3;
            ldsm4(r0, r1, r2, r3, bAddr + p * (16 * PITCH * 2) + kk);
            bf[2 * p][0] = r0; bf[2 * p][1] = r1;
            bf[2 * p + 1][0] = r2; bf[2 * p + 1][1] = r3;
        }
#pragma unroll
        for (int mi = 0; mi < 4; mi++)
#pragma unroll
            for (int ni = 0; ni < 4; ni++)
                mma_bf16(acc[mi][ni], a[mi], bf[ni]);
    }

    int r = lane >> 2, cp = (lane & 3) << 1;
    float gm = gamma[0];
#pragma unroll
    for (int mi = 0; mi < 4; mi++) {
#pragma unroll
        for (int half = 0; half < 2; half++) {
            int c = bc + wm * 64 + mi * 16 + half * 8 + r;
            float vs = gVsum[b * NC + c];
            const float* xr = x + ((size_t)b * NC + c) * NN + bn + wn * 32;
            float* orow = out + ((size_t)b * NC + c) * NN + bn + wn * 32;
#pragma unroll
            for (int ni = 0; ni < 4; ni++) {
                int n = ni * 8 + cp;
                float2 xv = *(const float2*)&xr[n];
                float tv0 = tailorS[wn * 32 + n];
                float tv1 = tailorS[wn * 32 + n + 1];
                float2 ov;
                ov.x = xv.x + gm * (vs + acc[mi][ni][half * 2]) * tv0;
                ov.y = xv.y + gm * (vs + acc[mi][ni][half * 2 + 1]) * tv1;
                *(float2*)&orow[n] = ov;
            }
        }
    }
}

// ---------------------------------------------------------------- launch
extern "C" void kernel_launch(void* const* d_in, const int* in_sizes, int n_in,
                              void* d_out, int out_size) {
    const float* x = (const float*)d_in[0];
    const float* Wq = (const float*)d_in[1];
    const float* bq = (const float*)d_in[2];
    const float* Wk = (const float*)d_in[3];
    const float* bk = (const float*)d_in[4];
    const float* Wv = (const float*)d_in[5];
    const float* bv = (const float*)d_in[6];
    const float* gamma = (const float*)d_in[7];
    float* out = (float*)d_out;
    (void)in_sizes; (void)n_in; (void)out_size;

    cudaFuncSetAttribute(conv_mma, cudaFuncAttributeMaxDynamicSharedMemorySize, 2 * STAGEB);
    cudaFuncSetAttribute(kv_mma, cudaFuncAttributeMaxDynamicSharedMemorySize, 2 * KVSTAGE);

    pack_weights<<<NI, 256>>>(Wq, bq, Wk, bk, Wv, bv);
    convert_x<<<dim3(NN / 32, NB), 256>>>(x);
    dummy_k<<<1, 32>>>();   // keeps conv_mma in the ncu capture slot (4th launch)
    conv_mma<<<dim3(NI / 128, NN / 128, NB), 256, 2 * STAGEB>>>();
    kv_mma<<<dim3(NC / 128, NSPLIT, NB), 256, 2 * KVSTAGE>>>();
    reduce_all<<<(NB * NC * NM + NB * NC + NB * NM + 255) / 256, 256>>>();
    final_mma<<<dim3(NC / 128, NN / 128, NB), 256>>>(x, gamma, out);
}

// round 17
// speedup vs baseline: 1.0606x; 1.0606x over previous
#include <cuda_runtime.h>
#include <cuda_bf16.h>
#include <cuda_fp16.h>
#include <cuda_fp8.h>
#include <cstdint>

#define NB 8
#define NC 512
#define NM 64
#define NN 4096
#define NI 640
#define EPSF 1e-6f
#define NSPLIT 16

// ---------------------------------------------------------------- scratch
__device__ __align__(16) unsigned char gW8[NI * NC];
__device__ float gBiasF[NI];
__device__ __align__(16) unsigned char gX8[(size_t)NB * NN * NC];    // fp8 x, [b,n,c]
__device__ __align__(16) unsigned char gV8[(size_t)NB * NC * NN];    // fp8 V, [b,c,n]
__device__ __align__(16) unsigned char gKn8[(size_t)NB * NM * NN];   // fp8 Kn*16, [b,m,n]
__device__ __align__(16) __half gQnTh[(size_t)NB * NN * NM];         // fp16 [b,n,m]
__device__ __align__(16) __nv_bfloat16 gMatP[(size_t)NSPLIT * NB * NC * NM]; // bf16 partials
__device__ __align__(16) __half gMatTh[(size_t)NB * NC * NM];        // fp16 [b,c,m]
__device__ float gVsumP[(size_t)32 * NB * NC];   // [nblk,b,c]
__device__ float gKsumP[(size_t)32 * NB * NM];   // [nblk,b,m]
__device__ float gKsum[NB * NM];
__device__ float gVsum[NB * NC];

// ---------------------------------------------------------------- helpers
__device__ __forceinline__ uint32_t smem_to_u32(const void* p) {
    uint32_t a;
    asm("{ .reg .u64 t; cvta.to.shared.u64 t, %1; cvt.u32.u64 %0, t; }" : "=r"(a) : "l"(p));
    return a;
}
__device__ __forceinline__ void ldsm4(uint32_t& r0, uint32_t& r1, uint32_t& r2,
                                      uint32_t& r3, uint32_t addr) {
    asm volatile("ldmatrix.sync.aligned.m8n8.x4.shared.b16 {%0,%1,%2,%3}, [%4];"
                 : "=r"(r0), "=r"(r1), "=r"(r2), "=r"(r3) : "r"(addr));
}
// f16 mma with f16 accumulators (2 regs = 4 halves)
__device__ __forceinline__ void mma_f16_h(uint32_t* d, const uint32_t* a, const uint32_t* b) {
    asm volatile(
        "mma.sync.aligned.m16n8k16.row.col.f16.f16.f16.f16 "
        "{%0,%1}, {%2,%3,%4,%5}, {%6,%7}, {%0,%1};"
        : "+r"(d[0]), "+r"(d[1])
        : "r"(a[0]), "r"(a[1]), "r"(a[2]), "r"(a[3]), "r"(b[0]), "r"(b[1]));
}
// fp8 mma with f16 accumulators (2 regs = 4 halves) — halves register pressure
__device__ __forceinline__ void mma_fp8_h(uint32_t* d, const uint32_t* a, const uint32_t* b) {
    asm volatile(
        "mma.sync.aligned.m16n8k32.row.col.f16.e4m3.e4m3.f16 "
        "{%0,%1}, {%2,%3,%4,%5}, {%6,%7}, {%0,%1};"
        : "+r"(d[0]), "+r"(d[1])
        : "r"(a[0]), "r"(a[1]), "r"(a[2]), "r"(a[3]), "r"(b[0]), "r"(b[1]));
}
__device__ __forceinline__ void cp_async16(uint32_t dst, const void* src) {
    asm volatile("cp.async.cg.shared.global [%0], [%1], 16;" :: "r"(dst), "l"(src));
}
#define CP_COMMIT() asm volatile("cp.async.commit_group;" ::: "memory")
#define CP_WAIT1() asm volatile("cp.async.wait_group 1;" ::: "memory")
#define CP_WAIT0() asm volatile("cp.async.wait_group 0;" ::: "memory")

#define PITCH 72     // 16-bit elems per smem row (144 B)
#define PITCHB 144   // bytes per fp8 smem row
#define QKPITCH 130  // bf16 pitch for epilogue QK tile

// ---------------------------------------------------------------- weights -> fp8 (x64)
__global__ void pack_weights(const float* __restrict__ Wq, const float* __restrict__ bq,
                             const float* __restrict__ Wk, const float* __restrict__ bk,
                             const float* __restrict__ Wv, const float* __restrict__ bv) {
    int i = blockIdx.x, t = threadIdx.x;
    const float* src; float bs;
    if (i < 64) { src = Wq + (size_t)i * NC; bs = bq[i]; }
    else if (i < 128) { src = Wk + (size_t)(i - 64) * NC; bs = bk[i - 64]; }
    else { src = Wv + (size_t)(i - 128) * NC; bs = bv[i - 128]; }
    unsigned char* dst = gW8 + (size_t)i * NC;
    for (int c = t; c < NC; c += 256)
        dst[c] = __nv_cvt_float_to_fp8(src[c] * 64.0f, __NV_SATFINITE, __NV_E4M3);
    if (t == 0) gBiasF[i] = bs;
}

// ---------------------------------------------------------------- x fp32[c,n] -> fp8[n,c]  (R14 tile version)
__global__ void convert_x(const float* __restrict__ x) {
    __shared__ float tile[32][33];
    int tx = threadIdx.x, ty = threadIdx.y;
    int n0 = blockIdx.x << 5, c0 = blockIdx.y << 5, b = blockIdx.z;
#pragma unroll
    for (int j = 0; j < 4; j++)
        tile[ty + 8 * j][tx] = x[((size_t)b * NC + c0 + ty + 8 * j) * NN + n0 + tx];
    __syncthreads();
    int t = ty * 32 + tx;
    int n = t >> 3, c4 = (t & 7) << 2;
    uint32_t pk = 0;
#pragma unroll
    for (int j = 0; j < 4; j++)
        pk |= (uint32_t)__nv_cvt_float_to_fp8(tile[c4 + j][n], __NV_SATFINITE, __NV_E4M3)
              << (8 * j);
    *(uint32_t*)&gX8[((size_t)b * NN + n0 + n) * NC + c0 + c4] = pk;
}

// ---------------------------------------------------------------- fused QKV conv (fp8, f16 acc, 2-stage, 3 CTAs/SM)
#define STAGEB 36864
__global__ void __launch_bounds__(256, 3) conv_mma() {
    extern __shared__ __align__(16) unsigned char dsm[];
    uint32_t base = smem_to_u32(dsm);
    int t = threadIdx.x, wid = t >> 5, lane = t & 31;
    int bi = blockIdx.x << 7, bn = blockIdx.y << 7, b = blockIdx.z;
    int wm = wid & 1, wn = wid >> 1;
    const unsigned char* Ag = gW8 + (size_t)bi * NC;
    const unsigned char* Bg = gX8 + ((size_t)b * NN + bn) * NC;
    uint32_t acc[4][4][2] = {};   // f16x2 accumulators: 32 regs
    int g = lane >> 3, lr = lane & 7;
    uint32_t aOff = (uint32_t)((wm * 64 + (g & 1) * 8 + lr) * PITCHB + (g >> 1) * 16);
    uint32_t bOff = 18432u + (uint32_t)((wn * 32 + (g >> 1) * 8 + lr) * PITCHB + (g & 1) * 16);
    int lrow = t >> 1, lcol = (t & 1) * 64;

#define CONV_PREFETCH(CH, ST) do { \
        int kb_ = (CH) * 128; \
        uint32_t s_ = (uint32_t)((ST) * STAGEB); \
        const unsigned char* a_ = Ag + (size_t)lrow * NC + kb_ + lcol; \
        uint32_t da_ = base + s_ + (uint32_t)(lrow * PITCHB + lcol); \
        cp_async16(da_, a_); cp_async16(da_ + 16, a_ + 16); \
        cp_async16(da_ + 32, a_ + 32); cp_async16(da_ + 48, a_ + 48); \
        const unsigned char* b_ = Bg + (size_t)lrow * NC + kb_ + lcol; \
        uint32_t db_ = base + s_ + 18432u + (uint32_t)(lrow * PITCHB + lcol); \
        cp_async16(db_, b_); cp_async16(db_ + 16, b_ + 16); \
        cp_async16(db_ + 32, b_ + 32); cp_async16(db_ + 48, b_ + 48); \
        CP_COMMIT(); \
    } while (0)

    CONV_PREFETCH(0, 0);

    for (int ch = 0; ch < 4; ch++) {
        CP_WAIT0();
        __syncthreads();
        if (ch < 3) CONV_PREFETCH(ch + 1, (ch + 1) & 1);
        uint32_t stg = base + (uint32_t)((ch & 1) * STAGEB);
#pragma unroll
        for (int ks = 0; ks < 4; ks++) {
            int kkb = ks * 32;
            uint32_t a[4][4], bf[4][2];
#pragma unroll
            for (int mi = 0; mi < 4; mi++)
                ldsm4(a[mi][0], a[mi][1], a[mi][2], a[mi][3],
                      stg + aOff + mi * (16 * PITCHB) + kkb);
#pragma unroll
            for (int p = 0; p < 2; p++) {
                uint32_t r0, r1, r2, r3;
                ldsm4(r0, r1, r2, r3, stg + bOff + p * (16 * PITCHB) + kkb);
                bf[2 * p][0] = r0; bf[2 * p][1] = r1;
                bf[2 * p + 1][0] = r2; bf[2 * p + 1][1] = r3;
            }
#pragma unroll
            for (int mi = 0; mi < 4; mi++)
#pragma unroll
                for (int ni = 0; ni < 4; ni++)
                    mma_fp8_h(acc[mi][ni], a[mi], bf[ni]);
        }
    }
    __syncthreads();  // guard: epilogue aliases stage smem

    const float INV64 = 0.015625f;
    int r = lane >> 2, cp = (lane & 3) << 1;

    if (bi == 0) {
        // -------- fused Q/K normalize epilogue --------
        __nv_bfloat16* sQK = (__nv_bfloat16*)dsm;  // [128][QKPITCH], aliases stage0
#pragma unroll
        for (int mi = 0; mi < 4; mi++) {
#pragma unroll
            for (int half = 0; half < 2; half++) {
                int localrow = wm * 64 + mi * 16 + half * 8 + r;
                float bias = gBiasF[localrow];
#pragma unroll
                for (int ni = 0; ni < 4; ni++) {
                    __half2 hv = *(__half2*)&acc[mi][ni][half];
                    float vx = __half2float(__low2half(hv)) * INV64 + bias;
                    float vy = __half2float(__high2half(hv)) * INV64 + bias;
                    __nv_bfloat162 v = __floats2bfloat162_rn(vx, vy);
                    *(uint32_t*)&sQK[localrow * QKPITCH + wn * 32 + ni * 8 + cp] =
                        *(uint32_t*)&v;
                }
            }
        }
        __syncthreads();
        int c = t & 127, part = t >> 7;
        if (part == 0) {
            float sq = 0.f;
#pragma unroll
            for (int m = 0; m < 64; m++) {
                float v = __bfloat162float(sQK[m * QKPITCH + c]);
                sq += v * v;
            }
            float rq = rsqrtf(sq + 1e-30f);
            __half tmp[64];
#pragma unroll
            for (int m = 0; m < 64; m++)
                tmp[m] = __float2half(__bfloat162float(sQK[m * QKPITCH + c]) * rq);
            uint4* dst = (uint4*)(gQnTh + ((size_t)b * NN + bn + c) * NM);
            const uint4* srcv = (const uint4*)tmp;
#pragma unroll
            for (int q8 = 0; q8 < 8; q8++) dst[q8] = srcv[q8];
        } else {
            float sk = 0.f;
#pragma unroll
            for (int m = 0; m < 64; m++) {
                float v = __bfloat162float(sQK[(64 + m) * QKPITCH + c]);
                sk += v * v;
            }
            float rk = rsqrtf(sk + 1e-30f);
#pragma unroll
            for (int m = 0; m < 64; m++) {
                float v = __bfloat162float(sQK[(64 + m) * QKPITCH + c]);
                float kn = v * rk;
                sQK[(64 + m) * QKPITCH + c] = __float2bfloat16(kn);
                gKn8[((size_t)b * NM + m) * NN + bn + c] =
                    __nv_cvt_float_to_fp8(kn * 16.0f, __NV_SATFINITE, __NV_E4M3);
            }
        }
        __syncthreads();
        int m = t >> 2, q = t & 3;
        float s = 0.f;
#pragma unroll
        for (int cc = 0; cc < 32; cc++)
            s += __bfloat162float(sQK[(64 + m) * QKPITCH + q * 32 + cc]);
        s += __shfl_xor_sync(0xFFFFFFFFu, s, 1);
        s += __shfl_xor_sync(0xFFFFFFFFu, s, 2);
        if (q == 0) gKsumP[((size_t)blockIdx.y * NB + b) * NM + m] = s;
    } else {
        // -------- V epilogue (fp8 out); sVs aliases stage smem --------
        float* sVs = (float*)dsm;  // [4][128]
#pragma unroll
        for (int mi = 0; mi < 4; mi++) {
#pragma unroll
            for (int half = 0; half < 2; half++) {
                int localrow = wm * 64 + mi * 16 + half * 8 + r;
                int ig = bi + localrow;
                float bias = gBiasF[ig];
                unsigned char* dst = gV8 + ((size_t)b * NC + ig - 128) * NN + bn + wn * 32;
                float rowsum = 0.f;
#pragma unroll
                for (int ni = 0; ni < 4; ni++) {
                    __half2 hv = *(__half2*)&acc[mi][ni][half];
                    float vx = __half2float(__low2half(hv)) * INV64 + bias;
                    float vy = __half2float(__high2half(hv)) * INV64 + bias;
                    rowsum += vx + vy;
                    uint16_t pk =
                        (uint16_t)__nv_cvt_float_to_fp8(vx, __NV_SATFINITE, __NV_E4M3) |
                        ((uint16_t)__nv_cvt_float_to_fp8(vy, __NV_SATFINITE, __NV_E4M3) << 8);
                    *(uint16_t*)&dst[ni * 8 + cp] = pk;
                }
                rowsum += __shfl_xor_sync(0xFFFFFFFFu, rowsum, 1);
                rowsum += __shfl_xor_sync(0xFFFFFFFFu, rowsum, 2);
                if ((lane & 3) == 0) sVs[wn * 128 + localrow] = rowsum;
            }
        }
        __syncthreads();
        if (t < 128) {
            float vp = sVs[0 * 128 + t] + sVs[1 * 128 + t] + sVs[2 * 128 + t] + sVs[3 * 128 + t];
            int c = bi - 128 + t;
            gVsumP[((size_t)blockIdx.y * NB + b) * NC + c] = vp;
        }
    }
}

// ---------------------------------------------------------------- KV contraction (fp8, f16 acc, 4 CTAs/SM)
#define KVSTAGE 27648  // A 128*144 + B 64*144
__global__ void __launch_bounds__(256, 4) kv_mma() {
    extern __shared__ __align__(16) unsigned char dsm[];
    uint32_t base = smem_to_u32(dsm);
    int t = threadIdx.x, wid = t >> 5, lane = t & 31;
    int bc = blockIdx.x << 7, split = blockIdx.y, b = blockIdx.z;
    int wm = wid & 3, wn = wid >> 2;
    const unsigned char* Ag = gV8 + ((size_t)b * NC + bc) * NN + split * 256;
    const unsigned char* Bg = gKn8 + (size_t)b * NM * NN + split * 256;
    uint32_t acc[2][4][2] = {};   // f16x2 accumulators: 16 regs
    int g = lane >> 3, lr = lane & 7;
    uint32_t aOff = (uint32_t)((wm * 32 + (g & 1) * 8 + lr) * PITCHB + (g >> 1) * 16);
    uint32_t bOff = 18432u + (uint32_t)((wn * 32 + (g >> 1) * 8 + lr) * PITCHB + (g & 1) * 16);
    int ar = t >> 1, acB = (t & 1) * 64;
    int br = t >> 2, bcB = (t & 3) * 32;

#define KV_PREFETCH(CH, ST) do { \
        int kb_ = (CH) * 128; \
        uint32_t s_ = (uint32_t)((ST) * KVSTAGE); \
        const unsigned char* a_ = Ag + (size_t)ar * NN + kb_ + acB; \
        uint32_t da_ = base + s_ + (uint32_t)(ar * PITCHB + acB); \
        cp_async16(da_, a_); cp_async16(da_ + 16, a_ + 16); \
        cp_async16(da_ + 32, a_ + 32); cp_async16(da_ + 48, a_ + 48); \
        const unsigned char* b_ = Bg + (size_t)br * NN + kb_ + bcB; \
        uint32_t db_ = base + s_ + 18432u + (uint32_t)(br * PITCHB + bcB); \
        cp_async16(db_, b_); cp_async16(db_ + 16, b_ + 16); \
        CP_COMMIT(); \
    } while (0)

    KV_PREFETCH(0, 0);

    for (int ch = 0; ch < 2; ch++) {
        if (ch < 1) { KV_PREFETCH(1, 1); CP_WAIT1(); }
        else CP_WAIT0();
        __syncthreads();
        uint32_t stg = base + (uint32_t)((ch & 1) * KVSTAGE);
#pragma unroll
        for (int ks = 0; ks < 4; ks++) {
            int kkb = ks * 32;
            uint32_t a[2][4], bf[4][2];
#pragma unroll
            for (int mi = 0; mi < 2; mi++)
                ldsm4(a[mi][0], a[mi][1], a[mi][2], a[mi][3],
                      stg + aOff + mi * (16 * PITCHB) + kkb);
#pragma unroll
            for (int p = 0; p < 2; p++) {
                uint32_t r0, r1, r2, r3;
                ldsm4(r0, r1, r2, r3, stg + bOff + p * (16 * PITCHB) + kkb);
                bf[2 * p][0] = r0; bf[2 * p][1] = r1;
                bf[2 * p + 1][0] = r2; bf[2 * p + 1][1] = r3;
            }
#pragma unroll
            for (int mi = 0; mi < 2; mi++)
#pragma unroll
                for (int ni = 0; ni < 4; ni++)
                    mma_fp8_h(acc[mi][ni], a[mi], bf[ni]);
        }
        __syncthreads();
    }

    const float INV16 = 0.0625f;
    int r = lane >> 2, cp = (lane & 3) << 1;
#pragma unroll
    for (int mi = 0; mi < 2; mi++) {
#pragma unroll
        for (int half = 0; half < 2; half++) {
            int c = bc + wm * 32 + mi * 16 + half * 8 + r;
            __nv_bfloat16* dst = gMatP + (((size_t)split * NB + b) * NC + c) * NM + wn * 32;
#pragma unroll
            for (int ni = 0; ni < 4; ni++) {
                __half2 hv = *(__half2*)&acc[mi][ni][half];
                __nv_bfloat162 v = __floats2bfloat162_rn(
                    __half2float(__low2half(hv)) * INV16,
                    __half2float(__high2half(hv)) * INV16);
                *(uint32_t*)&dst[ni * 8 + cp] = *(uint32_t*)&v;
            }
        }
    }
}

// ---------------------------------------------------------------- combined reductions
__global__ void reduce_all() {
    int idx = blockIdx.x * 256 + threadIdx.x;
    const int NMAT = NB * NC * NM;
    const int NVS = NB * NC;
    if (idx < NMAT) {
        float s = 0.f;
#pragma unroll
        for (int sp = 0; sp < NSPLIT; sp++)
            s += __bfloat162float(gMatP[(size_t)sp * NMAT + idx]);
        gMatTh[idx] = __float2half(s);
    } else if (idx < NMAT + NVS) {
        int i = idx - NMAT;
        int b = i >> 9, c = i & 511;
        float s = 0.f;
#pragma unroll
        for (int blk = 0; blk < 32; blk++)
            s += gVsumP[((size_t)blk * NB + b) * NC + c];
        gVsum[b * NC + c] = s;
    } else if (idx < NMAT + NVS + NB * NM) {
        int i = idx - NMAT - NVS;
        int b = i >> 6, m = i & 63;
        float s = 0.f;
#pragma unroll
        for (int blk = 0; blk < 32; blk++)
            s += gKsumP[((size_t)blk * NB + b) * NM + m];
        gKsum[b * NM + m] = s;
    }
}

// ---------------------------------------------------------------- final GEMM (fp16, f16 acc) + tailor + epilogue
__global__ void __launch_bounds__(256, 3) final_mma(
        const float* __restrict__ x, const float* __restrict__ gamma,
        float* __restrict__ out) {
    __shared__ __align__(16) __half As[128][PITCH];
    __shared__ __align__(16) __half Bs[128][PITCH];
    __shared__ float ksS[64];
    __shared__ float tailorS[128];
    int t = threadIdx.x, wid = t >> 5, lane = t & 31;
    int bc = blockIdx.x << 7, bn = blockIdx.y << 7, b = blockIdx.z;
    int wm = wid & 1, wn = wid >> 1;
    const __half* Ag = gMatTh + ((size_t)b * NC + bc) * NM;
    const __half* Bg = gQnTh + ((size_t)b * NN + bn) * NM;
    uint32_t acc[4][4][2] = {};   // f16x2 accumulators: 32 regs
    uint32_t aBase = smem_to_u32(As), bBase = smem_to_u32(Bs);
    int g = lane >> 3, lr = lane & 7;
    uint32_t aAddr = aBase + (uint32_t)(((wm * 64 + (g & 1) * 8 + lr) * PITCH + (g >> 1) * 8) * 2);
    uint32_t bAddr = bBase + (uint32_t)(((wn * 32 + (g >> 1) * 8 + lr) * PITCH + (g & 1) * 8) * 2);
    {
        int row = t >> 1, col = (t & 1) * 32;
        const uint4* sa = (const uint4*)(Ag + (size_t)row * NM + col);
        uint4* da = (uint4*)(&As[row][col]);
        da[0] = sa[0]; da[1] = sa[1]; da[2] = sa[2]; da[3] = sa[3];
        const uint4* sb = (const uint4*)(Bg + (size_t)row * NM + col);
        uint4* db = (uint4*)(&Bs[row][col]);
        db[0] = sb[0]; db[1] = sb[1]; db[2] = sb[2]; db[3] = sb[3];
    }
    if (t < 64) ksS[t] = gKsum[b * NM + t] + EPSF;
    __syncthreads();
    if (t < 128) {
        const __half2* qr = (const __half2*)&Bs[t][0];
        float s = 0.f;
#pragma unroll
        for (int mm = 0; mm < 32; mm++) {
            float2 f = __half22float2(qr[mm]);
            s += f.x * ksS[2 * mm] + f.y * ksS[2 * mm + 1];
        }
        tailorS[t] = 1.0f / ((float)NN + s);
    }
    __syncthreads();
#pragma unroll
    for (int ks = 0; ks < 4; ks++) {
        int kk = ks * 32;
        uint32_t a[4][4], bf[4][2];
#pragma unroll
        for (int mi = 0; mi < 4; mi++)
            ldsm4(a[mi][0], a[mi][1], a[mi][2], a[mi][3],
                  aAddr + mi * (16 * PITCH * 2) + kk);
#pragma unroll
        for (int p = 0; p < 2; p++) {
            uint32_t r0, r1, r2, r3;
            ldsm4(r0, r1, r2, r3, bAddr + p * (16 * PITCH * 2) + kk);
            bf[2 * p][0] = r0; bf[2 * p][1] = r1;
            bf[2 * p + 1][0] = r2; bf[2 * p + 1][1] = r3;
        }
#pragma unroll
        for (int mi = 0; mi < 4; mi++)
#pragma unroll
            for (int ni = 0; ni < 4; ni++)
                mma_f16_h(acc[mi][ni], a[mi], bf[ni]);
    }

    int r = lane >> 2, cp = (lane & 3) << 1;
    float gm = gamma[0];
#pragma unroll
    for (int mi = 0; mi < 4; mi++) {
#pragma unroll
        for (int half = 0; half < 2; half++) {
            int c = bc + wm * 64 + mi * 16 + half * 8 + r;
            float vs = gVsum[b * NC + c];
            const float* xr = x + ((size_t)b * NC + c) * NN + bn + wn * 32;
            float* orow = out + ((size_t)b * NC + c) * NN + bn + wn * 32;
#pragma unroll
            for (int ni = 0; ni < 4; ni++) {
                int n = ni * 8 + cp;
                float2 xv = *(const float2*)&xr[n];
                float tv0 = tailorS[wn * 32 + n];
                float tv1 = tailorS[wn * 32 + n + 1];
                __half2 hv = *(__half2*)&acc[mi][ni][half];
                float2 av = __half22float2(hv);
                float2 ov;
                ov.x = xv.x + gm * (vs + av.x) * tv0;
                ov.y = xv.y + gm * (vs + av.y) * tv1;
                *(float2*)&orow[n] = ov;
            }
        }
    }
}

// ---------------------------------------------------------------- launch
extern "C" void kernel_launch(void* const* d_in, const int* in_sizes, int n_in,
                              void* d_out, int out_size) {
    const float* x = (const float*)d_in[0];
    const float* Wq = (const float*)d_in[1];
    const float* bq = (const float*)d_in[2];
    const float* Wk = (const float*)d_in[3];
    const float* bk = (const float*)d_in[4];
    const float* Wv = (const float*)d_in[5];
    const float* bv = (const float*)d_in[6];
    const float* gamma = (const float*)d_in[7];
    float* out = (float*)d_out;
    (void)in_sizes; (void)n_in; (void)out_size;

    cudaFuncSetAttribute(conv_mma, cudaFuncAttributeMaxDynamicSharedMemorySize, 2 * STAGEB);
    cudaFuncSetAttribute(kv_mma, cudaFuncAttributeMaxDynamicSharedMemorySize, 2 * KVSTAGE);

    pack_weights<<<NI, 256>>>(Wq, bq, Wk, bk, Wv, bv);
    convert_x<<<dim3(NN / 32, NC / 32, NB), dim3(32, 8)>>>(x);
    conv_mma<<<dim3(NI / 128, NN / 128, NB), 256, 2 * STAGEB>>>();
    kv_mma<<<dim3(NC / 128, NSPLIT, NB), 256, 2 * KVSTAGE>>>();   // 4th launch -> ncu slot
    reduce_all<<<(NB * NC * NM + NB * NC + NB * NM + 255) / 256, 256>>>();
    final_mma<<<dim3(NC / 128, NN / 128, NB), 256>>>(x, gamma, out);
}